// round 5
// baseline (speedup 1.0000x reference)
#include <cuda_runtime.h>
#include <cuda_bf16.h>
#include <math.h>

// ---------------------------------------------------------------------------
// Problem constants
// ---------------------------------------------------------------------------
#define NPTS   32768
#define SAMP   16
#define DIM    256
#define PH     128
#define QKVD   768        // 3*DIM
#define SCALE  1.0f
#define MAXBP  128        // max breakpoints
#define MAXIV  129        // max intervals

// ---------------------------------------------------------------------------
// Device scratch (static: no runtime allocation allowed)
// ---------------------------------------------------------------------------
__device__ float g_qkv[(size_t)NPTS * QKVD];   // 96 MB: q|k|v rows of 768
__device__ float g_attn[(size_t)NPTS * DIM];   // 32 MB: attention output
__device__ float g_bp[MAXBP];                  // sorted breakpoints
__device__ int   g_nbp;                        // breakpoint count
__device__ float g_A[MAXIV * DIM];             // per-interval slope
__device__ float g_C[MAXIV * DIM];             // per-interval intercept

__device__ __forceinline__ float dev_inf() { return __int_as_float(0x7f800000); }

// ---------------------------------------------------------------------------
// P1: compute + sort pos-MLP breakpoints t_j = -b1_j / w1_j  (1 block, 128 thr)
// ---------------------------------------------------------------------------
__global__ void breakpoints_kernel(const float* __restrict__ Wp1,
                                   const float* __restrict__ bp1)
{
    __shared__ float vals[PH];
    int j = threadIdx.x;                       // 0..127
    float w1 = Wp1[j], b1 = bp1[j];
    float t = -b1 / w1;
    bool valid = (w1 != 0.0f) && isfinite(t) && (t > 0.0f);
    vals[j] = valid ? t : dev_inf();
    int cnt = __syncthreads_count(valid ? 1 : 0);
    // rank sort (O(128^2), trivial). Ties broken by index -> unique ranks.
    float tv = vals[j];
    int rank = 0;
    #pragma unroll 4
    for (int jj = 0; jj < PH; jj++) {
        float o = vals[jj];
        if (o < tv || (o == tv && jj < j)) rank++;
    }
    if (rank < MAXBP) g_bp[rank] = tv;         // valid ones land in [0, cnt)
    if (j == 0) g_nbp = cnt;
}

// ---------------------------------------------------------------------------
// P2: per-interval affine coefficients.  grid = 129 blocks x 256 threads.
//   interval iv covers d in (t_{iv-1}, t_iv); representative point decides
//   the relu active set, which is constant inside the interval.
// ---------------------------------------------------------------------------
__global__ void pos_coeff_kernel(const float* __restrict__ Wp1,
                                 const float* __restrict__ bp1,
                                 const float* __restrict__ Wp2)
{
    __shared__ float s_w1[PH], s_b1[PH];
    int M = g_nbp;
    int iv = blockIdx.x;
    if (iv > M) return;
    int o = threadIdx.x;                       // output channel 0..255
    if (o < PH) { s_w1[o] = Wp1[o]; s_b1[o] = bp1[o]; }
    __syncthreads();

    float lo  = (iv == 0) ? 0.0f : g_bp[iv - 1];
    float rep = (iv == M) ? (lo + 1.0f) : 0.5f * (lo + g_bp[iv]);

    const float* w2row = Wp2 + (size_t)o * PH; // Wp2 is [DIM, PH] row-major
    float a = 0.0f, c = 0.0f;
    #pragma unroll 8
    for (int j = 0; j < PH; j++) {
        if (fmaf(rep, s_w1[j], s_b1[j]) > 0.0f) {
            a = fmaf(s_w1[j], w2row[j], a);
            c = fmaf(s_b1[j], w2row[j], c);
        }
    }
    g_A[iv * DIM + o] = a;
    g_C[iv * DIM + o] = c;
}

// ---------------------------------------------------------------------------
// SGEMM:  C[M,N] = A[M,K] * B[N,K]^T + bias[N]
//   128x64 block tile, 8x4 thread tile, 256 threads, BK=16.
//   M%128==0, N%64==0, K%16==0 guaranteed by our shapes.
// ---------------------------------------------------------------------------
#define BM 128
#define BN 64
#define BK 16
#define TM 8
#define TN 4

__global__ void __launch_bounds__(256)
sgemm_bias_kernel(const float* __restrict__ A, const float* __restrict__ B,
                  const float* __restrict__ bias, float* __restrict__ C,
                  int K, int ldc)
{
    __shared__ __align__(16) float As[BK][BM];
    __shared__ __align__(16) float Bs[BK][BN];

    int tid = threadIdx.x;
    int tx  = tid & 15;          // n-dim (16 * TN=4 -> 64)
    int ty  = tid >> 4;          // m-dim (16 * TM=8 -> 128)
    int m0  = blockIdx.y * BM;
    int n0  = blockIdx.x * BN;

    float acc[TM][TN];
    #pragma unroll
    for (int i = 0; i < TM; i++)
        #pragma unroll
        for (int j = 0; j < TN; j++) acc[i][j] = 0.0f;

    for (int k0 = 0; k0 < K; k0 += BK) {
        // A tile: 128 rows x 16 cols = 512 float4; 2 per thread
        #pragma unroll
        for (int r = 0; r < 2; r++) {
            int L = tid + r * 256;
            int row = L >> 2, c4 = L & 3;
            float4 v = *(const float4*)(A + (size_t)(m0 + row) * K + k0 + c4 * 4);
            As[c4 * 4 + 0][row] = v.x;
            As[c4 * 4 + 1][row] = v.y;
            As[c4 * 4 + 2][row] = v.z;
            As[c4 * 4 + 3][row] = v.w;
        }
        // B tile: 64 rows x 16 cols = 256 float4; 1 per thread
        {
            int row = tid >> 2, c4 = tid & 3;
            float4 v = *(const float4*)(B + (size_t)(n0 + row) * K + k0 + c4 * 4);
            Bs[c4 * 4 + 0][row] = v.x;
            Bs[c4 * 4 + 1][row] = v.y;
            Bs[c4 * 4 + 2][row] = v.z;
            Bs[c4 * 4 + 3][row] = v.w;
        }
        __syncthreads();

        #pragma unroll
        for (int kk = 0; kk < BK; kk++) {
            float4 a0 = *(const float4*)&As[kk][ty * TM];
            float4 a1 = *(const float4*)&As[kk][ty * TM + 4];
            float4 b0 = *(const float4*)&Bs[kk][tx * TN];
            float ra[TM] = {a0.x, a0.y, a0.z, a0.w, a1.x, a1.y, a1.z, a1.w};
            float rb[TN] = {b0.x, b0.y, b0.z, b0.w};
            #pragma unroll
            for (int i = 0; i < TM; i++)
                #pragma unroll
                for (int j = 0; j < TN; j++)
                    acc[i][j] = fmaf(ra[i], rb[j], acc[i][j]);
        }
        __syncthreads();
    }

    int nbase = n0 + tx * TN;
    float4 bv = *(const float4*)(bias + nbase);
    float bb[TN] = {bv.x, bv.y, bv.z, bv.w};
    #pragma unroll
    for (int i = 0; i < TM; i++) {
        int m = m0 + ty * TM + i;
        float4 ov;
        ov.x = acc[i][0] + bb[0];
        ov.y = acc[i][1] + bb[1];
        ov.z = acc[i][2] + bb[2];
        ov.w = acc[i][3] + bb[3];
        *(float4*)(C + (size_t)m * ldc + nbase) = ov;
    }
}

// ---------------------------------------------------------------------------
// Attention core: one block per point n, one thread per channel i (256 thr).
// Softmax over S=16 is INDEPENDENT per channel (axis=1 of [N,S,H,HD]).
// Two-pass (max, then exp/accumulate) for ILP.
// ---------------------------------------------------------------------------
__global__ void __launch_bounds__(256)
attn_kernel(const float* __restrict__ pos,
            const int*   __restrict__ attn_index,
            const int*   __restrict__ mask,
            const float* __restrict__ bp2)
{
    int n = blockIdx.x;
    int i = threadIdx.x;

    __shared__ float s_d[SAMP];
    __shared__ int   s_idx[SAMP];
    __shared__ int   s_iv[SAMP];
    __shared__ int   s_msk[SAMP];

    if (i < SAMP) {
        int idx = attn_index[n * SAMP + i];
        s_idx[i] = idx;
        float dx = pos[idx * 3 + 0] - pos[n * 3 + 0];
        float dy = pos[idx * 3 + 1] - pos[n * 3 + 1];
        float dz = pos[idx * 3 + 2] - pos[n * 3 + 2];
        float d = sqrtf(dx * dx + dy * dy + dz * dz);
        s_d[i] = d;
        int M = g_nbp, c = 0;
        for (int j = 0; j < M; j++) c += (g_bp[j] < d);
        s_iv[i] = c;
        s_msk[i] = mask[n * SAMP + i];
    }
    __syncthreads();

    float q  = g_qkv[(size_t)n * QKVD + i];
    float b2 = bp2[i];

    float w[SAMP], vr[SAMP];
    float mx = -dev_inf();
    #pragma unroll
    for (int s = 0; s < SAMP; s++) {
        int idx = s_idx[s];
        int iv  = s_iv[s];
        float rel = SCALE * (fmaf(s_d[s], g_A[iv * DIM + i], g_C[iv * DIM + i]) + b2);
        float xk = g_qkv[(size_t)idx * QKVD + DIM + i];
        float xv = g_qkv[(size_t)idx * QKVD + 2 * DIM + i];
        float ww = fmaf(xk, q, rel);
        w[s]  = s_msk[s] ? -dev_inf() : ww;
        vr[s] = xv + rel;
        mx = fmaxf(mx, w[s]);
    }
    float l = 0.0f, acc = 0.0f;
    #pragma unroll
    for (int s = 0; s < SAMP; s++) {
        float p = __expf(w[s] - mx);   // masked: exp(-inf) = 0
        l += p;
        acc = fmaf(p, vr[s], acc);
    }
    g_attn[(size_t)n * DIM + i] = acc / l;
}

// ---------------------------------------------------------------------------
// Launch
// ---------------------------------------------------------------------------
extern "C" void kernel_launch(void* const* d_in, const int* in_sizes, int n_in,
                              void* d_out, int out_size)
{
    const float* x          = (const float*)d_in[0];
    const float* pos        = (const float*)d_in[1];
    const int*   attn_index = (const int*)  d_in[2];
    const int*   mask       = (const int*)  d_in[3];
    const float* Wqkv       = (const float*)d_in[4];
    const float* bqkv       = (const float*)d_in[5];
    const float* Wp1        = (const float*)d_in[6];
    const float* bp1        = (const float*)d_in[7];
    const float* Wp2        = (const float*)d_in[8];
    const float* bp2        = (const float*)d_in[9];
    const float* Wo         = (const float*)d_in[10];
    const float* bo         = (const float*)d_in[11];
    float*       out        = (float*)d_out;

    float* qkv_ptr  = nullptr;
    float* attn_ptr = nullptr;
    cudaGetSymbolAddress((void**)&qkv_ptr,  g_qkv);
    cudaGetSymbolAddress((void**)&attn_ptr, g_attn);

    // 1. pos-MLP piecewise-linear precompute (cheap, every launch)
    breakpoints_kernel<<<1, PH>>>(Wp1, bp1);
    pos_coeff_kernel<<<MAXIV, DIM>>>(Wp1, bp1, Wp2);

    // 2. QKV projection: [N,256] x [768,256]^T -> [N,768]
    {
        dim3 grid(QKVD / BN, NPTS / BM);
        sgemm_bias_kernel<<<grid, 256>>>(x, Wqkv, bqkv, qkv_ptr, DIM, QKVD);
    }

    // 3. Fused gather + pos-bias + per-channel softmax + value reduce
    attn_kernel<<<NPTS, DIM>>>(pos, attn_index, mask, bp2);

    // 4. Output projection: [N,256] x [256,256]^T -> [N,256]
    {
        dim3 grid(DIM / BN, NPTS / BM);
        sgemm_bias_kernel<<<grid, 256>>>(attn_ptr, Wo, bo, out, DIM, DIM);
    }
}

// round 6
// speedup vs baseline: 1.1129x; 1.1129x over previous
#include <cuda_runtime.h>
#include <cuda_bf16.h>
#include <math.h>

// ---------------------------------------------------------------------------
// Problem constants
// ---------------------------------------------------------------------------
#define NPTS   32768
#define SAMP   16
#define DIM    256
#define PH     128
#define QKVD   768        // 3*DIM
#define SCALE  1.0f
#define MAXBP  128
#define MAXIV  129

// ---------------------------------------------------------------------------
// Device scratch
// ---------------------------------------------------------------------------
__device__ float g_qkv[(size_t)NPTS * QKVD];   // 96 MB
__device__ float g_attn[(size_t)NPTS * DIM];   // 32 MB
__device__ float g_bp[MAXBP];
__device__ int   g_nbp;
__device__ float g_A[MAXIV * DIM];
__device__ float g_C[MAXIV * DIM];

__device__ __forceinline__ float dev_inf() { return __int_as_float(0x7f800000); }

// ---------------------------------------------------------------------------
// P1: breakpoints of the piecewise-linear pos-MLP
// ---------------------------------------------------------------------------
__global__ void breakpoints_kernel(const float* __restrict__ Wp1,
                                   const float* __restrict__ bp1)
{
    __shared__ float vals[PH];
    int j = threadIdx.x;
    float w1 = Wp1[j], b1 = bp1[j];
    float t = -b1 / w1;
    bool valid = (w1 != 0.0f) && isfinite(t) && (t > 0.0f);
    vals[j] = valid ? t : dev_inf();
    int cnt = __syncthreads_count(valid ? 1 : 0);
    float tv = vals[j];
    int rank = 0;
    #pragma unroll 4
    for (int jj = 0; jj < PH; jj++) {
        float o = vals[jj];
        if (o < tv || (o == tv && jj < j)) rank++;
    }
    if (rank < MAXBP) g_bp[rank] = tv;
    if (j == 0) g_nbp = cnt;
}

// ---------------------------------------------------------------------------
// P2: per-interval affine coefficients
// ---------------------------------------------------------------------------
__global__ void pos_coeff_kernel(const float* __restrict__ Wp1,
                                 const float* __restrict__ bp1,
                                 const float* __restrict__ Wp2)
{
    __shared__ float s_w1[PH], s_b1[PH];
    int M = g_nbp;
    int iv = blockIdx.x;
    if (iv > M) return;
    int o = threadIdx.x;
    if (o < PH) { s_w1[o] = Wp1[o]; s_b1[o] = bp1[o]; }
    __syncthreads();

    float lo  = (iv == 0) ? 0.0f : g_bp[iv - 1];
    float rep = (iv == M) ? (lo + 1.0f) : 0.5f * (lo + g_bp[iv]);

    const float* w2row = Wp2 + (size_t)o * PH;
    float a = 0.0f, c = 0.0f;
    #pragma unroll 8
    for (int j = 0; j < PH; j++) {
        if (fmaf(rep, s_w1[j], s_b1[j]) > 0.0f) {
            a = fmaf(s_w1[j], w2row[j], a);
            c = fmaf(s_b1[j], w2row[j], c);
        }
    }
    g_A[iv * DIM + o] = a;
    g_C[iv * DIM + o] = c;
}

// ---------------------------------------------------------------------------
// SGEMM v2: C[M,N] = A[M,K]*B[N,K]^T + bias
//   128x128 tile, BK=16, 256 threads, 8x8 microtile, double-buffered smem,
//   inner product via packed fma.rn.f32x2 (sm_100+).
// ---------------------------------------------------------------------------
#define BM 128
#define BN 128
#define BK 16

__global__ void __launch_bounds__(256, 2)
sgemm_bias_db(const float* __restrict__ A, const float* __restrict__ B,
              const float* __restrict__ bias, float* __restrict__ C,
              int K, int ldc)
{
    __shared__ __align__(16) float As[2][BK][BM];
    __shared__ __align__(16) float Bs[2][BK][BN];

    const int tid = threadIdx.x;
    const int tx  = tid & 15;          // n: 16 * 8 = 128
    const int ty  = tid >> 4;          // m: 16 * 8 = 128
    const int m0  = blockIdx.y * BM;
    const int n0  = blockIdx.x * BN;

    const int lrow = tid >> 2;         // 0..63
    const int lc4  = tid & 3;          // 0..3 (16B column chunk)

    const float* Ap = A + (size_t)(m0 + lrow) * K + lc4 * 4;
    const float* Bp = B + (size_t)(n0 + lrow) * K + lc4 * 4;
    const size_t rstep = (size_t)64 * K;

    float4 pa0 = *(const float4*)(Ap);
    float4 pa1 = *(const float4*)(Ap + rstep);
    float4 pb0 = *(const float4*)(Bp);
    float4 pb1 = *(const float4*)(Bp + rstep);

    unsigned long long acc[8][4];      // each holds a packed f32x2 column pair
    #pragma unroll
    for (int i2 = 0; i2 < 8; i2++)
        #pragma unroll
        for (int j2 = 0; j2 < 4; j2++) acc[i2][j2] = 0ULL;

    // prologue store
    {
        As[0][lc4*4+0][lrow]    = pa0.x; As[0][lc4*4+1][lrow]    = pa0.y;
        As[0][lc4*4+2][lrow]    = pa0.z; As[0][lc4*4+3][lrow]    = pa0.w;
        As[0][lc4*4+0][lrow+64] = pa1.x; As[0][lc4*4+1][lrow+64] = pa1.y;
        As[0][lc4*4+2][lrow+64] = pa1.z; As[0][lc4*4+3][lrow+64] = pa1.w;
        Bs[0][lc4*4+0][lrow]    = pb0.x; Bs[0][lc4*4+1][lrow]    = pb0.y;
        Bs[0][lc4*4+2][lrow]    = pb0.z; Bs[0][lc4*4+3][lrow]    = pb0.w;
        Bs[0][lc4*4+0][lrow+64] = pb1.x; Bs[0][lc4*4+1][lrow+64] = pb1.y;
        Bs[0][lc4*4+2][lrow+64] = pb1.z; Bs[0][lc4*4+3][lrow+64] = pb1.w;
    }
    __syncthreads();

    const int nk = K / BK;
    int buf = 0;
    for (int kt = 0; kt < nk; kt++) {
        if (kt + 1 < nk) {
            const float* An = Ap + (kt + 1) * BK;
            const float* Bn = Bp + (kt + 1) * BK;
            pa0 = *(const float4*)(An);
            pa1 = *(const float4*)(An + rstep);
            pb0 = *(const float4*)(Bn);
            pb1 = *(const float4*)(Bn + rstep);
        }
        #pragma unroll
        for (int kk = 0; kk < BK; kk++) {
            float4 af0 = *(const float4*)&As[buf][kk][ty * 8];
            float4 af1 = *(const float4*)&As[buf][kk][ty * 8 + 4];
            ulonglong2 bf0 = *(const ulonglong2*)&Bs[buf][kk][tx * 8];
            ulonglong2 bf1 = *(const ulonglong2*)&Bs[buf][kk][tx * 8 + 4];
            float ar[8] = {af0.x, af0.y, af0.z, af0.w, af1.x, af1.y, af1.z, af1.w};
            unsigned long long br[4] = {bf0.x, bf0.y, bf1.x, bf1.y};
            #pragma unroll
            for (int i2 = 0; i2 < 8; i2++) {
                unsigned long long a2;
                asm("mov.b64 %0, {%1, %1};" : "=l"(a2) : "f"(ar[i2]));
                #pragma unroll
                for (int j2 = 0; j2 < 4; j2++)
                    asm("fma.rn.f32x2 %0, %1, %2, %0;"
                        : "+l"(acc[i2][j2]) : "l"(a2), "l"(br[j2]));
            }
        }
        if (kt + 1 < nk) {
            int nb = buf ^ 1;
            As[nb][lc4*4+0][lrow]    = pa0.x; As[nb][lc4*4+1][lrow]    = pa0.y;
            As[nb][lc4*4+2][lrow]    = pa0.z; As[nb][lc4*4+3][lrow]    = pa0.w;
            As[nb][lc4*4+0][lrow+64] = pa1.x; As[nb][lc4*4+1][lrow+64] = pa1.y;
            As[nb][lc4*4+2][lrow+64] = pa1.z; As[nb][lc4*4+3][lrow+64] = pa1.w;
            Bs[nb][lc4*4+0][lrow]    = pb0.x; Bs[nb][lc4*4+1][lrow]    = pb0.y;
            Bs[nb][lc4*4+2][lrow]    = pb0.z; Bs[nb][lc4*4+3][lrow]    = pb0.w;
            Bs[nb][lc4*4+0][lrow+64] = pb1.x; Bs[nb][lc4*4+1][lrow+64] = pb1.y;
            Bs[nb][lc4*4+2][lrow+64] = pb1.z; Bs[nb][lc4*4+3][lrow+64] = pb1.w;
            __syncthreads();
            buf = nb;
        }
    }

    // epilogue: unpack, add bias, store
    float4 bv0 = *(const float4*)(bias + n0 + tx * 8);
    float4 bv1 = *(const float4*)(bias + n0 + tx * 8 + 4);
    #pragma unroll
    for (int i2 = 0; i2 < 8; i2++) {
        int m = m0 + ty * 8 + i2;
        float c0x, c0y, c1x, c1y, c2x, c2y, c3x, c3y;
        asm("mov.b64 {%0, %1}, %2;" : "=f"(c0x), "=f"(c0y) : "l"(acc[i2][0]));
        asm("mov.b64 {%0, %1}, %2;" : "=f"(c1x), "=f"(c1y) : "l"(acc[i2][1]));
        asm("mov.b64 {%0, %1}, %2;" : "=f"(c2x), "=f"(c2y) : "l"(acc[i2][2]));
        asm("mov.b64 {%0, %1}, %2;" : "=f"(c3x), "=f"(c3y) : "l"(acc[i2][3]));
        float4 o0 = {c0x + bv0.x, c0y + bv0.y, c1x + bv0.z, c1y + bv0.w};
        float4 o1 = {c2x + bv1.x, c2y + bv1.y, c3x + bv1.z, c3y + bv1.w};
        *(float4*)(C + (size_t)m * ldc + n0 + tx * 8)     = o0;
        *(float4*)(C + (size_t)m * ldc + n0 + tx * 8 + 4) = o1;
    }
}

// ---------------------------------------------------------------------------
// Attention core. Hot path specialized for g_nbp==0 (single interval):
// A/C hoisted out of the sample loop; rel recomputed (1 FMA) in pass 2
// so only w[] and xv[] arrays are live -> lower regs, higher occupancy.
// ---------------------------------------------------------------------------
__global__ void __launch_bounds__(256, 5)
attn_kernel(const float* __restrict__ pos,
            const int*   __restrict__ attn_index,
            const int*   __restrict__ mask,
            const float* __restrict__ bp2)
{
    int n = blockIdx.x;
    int i = threadIdx.x;

    __shared__ float s_d[SAMP];
    __shared__ int   s_idx[SAMP];
    __shared__ int   s_iv[SAMP];
    __shared__ int   s_msk[SAMP];

    if (i < SAMP) {
        int idx = attn_index[n * SAMP + i];
        s_idx[i] = idx;
        float dx = pos[idx * 3 + 0] - pos[n * 3 + 0];
        float dy = pos[idx * 3 + 1] - pos[n * 3 + 1];
        float dz = pos[idx * 3 + 2] - pos[n * 3 + 2];
        float d = sqrtf(dx * dx + dy * dy + dz * dz);
        s_d[i] = d;
        int M = g_nbp, c = 0;
        for (int j = 0; j < M; j++) c += (g_bp[j] < d);
        s_iv[i] = c;
        s_msk[i] = mask[n * SAMP + i];
    }
    __syncthreads();

    float q  = g_qkv[(size_t)n * QKVD + i];
    float b2 = bp2[i];

    if (g_nbp == 0) {
        // uniform hot path: one interval, coefficients invariant over samples
        float a  = SCALE * g_A[i];
        float cb = SCALE * (g_C[i] + b2);

        float w[SAMP], xvv[SAMP];
        float mx = -dev_inf();
        #pragma unroll
        for (int s = 0; s < SAMP; s++) {
            int idx = s_idx[s];
            float rel = fmaf(s_d[s], a, cb);
            float xk = g_qkv[(size_t)idx * QKVD + DIM + i];
            xvv[s]   = g_qkv[(size_t)idx * QKVD + 2 * DIM + i];
            float ww = fmaf(xk, q, rel);
            w[s] = s_msk[s] ? -dev_inf() : ww;
            mx = fmaxf(mx, w[s]);
        }
        float l = 0.0f, accv = 0.0f;
        #pragma unroll
        for (int s = 0; s < SAMP; s++) {
            float p = __expf(w[s] - mx);
            l += p;
            accv = fmaf(p, xvv[s] + fmaf(s_d[s], a, cb), accv);
        }
        g_attn[(size_t)n * DIM + i] = accv / l;
    } else {
        // general path (cold for this dataset)
        float w[SAMP], vr[SAMP];
        float mx = -dev_inf();
        #pragma unroll 4
        for (int s = 0; s < SAMP; s++) {
            int idx = s_idx[s];
            int iv  = s_iv[s];
            float rel = SCALE * (fmaf(s_d[s], g_A[iv * DIM + i], g_C[iv * DIM + i]) + b2);
            float xk = g_qkv[(size_t)idx * QKVD + DIM + i];
            float xv = g_qkv[(size_t)idx * QKVD + 2 * DIM + i];
            float ww = fmaf(xk, q, rel);
            w[s]  = s_msk[s] ? -dev_inf() : ww;
            vr[s] = xv + rel;
            mx = fmaxf(mx, w[s]);
        }
        float l = 0.0f, accv = 0.0f;
        #pragma unroll 4
        for (int s = 0; s < SAMP; s++) {
            float p = __expf(w[s] - mx);
            l += p;
            accv = fmaf(p, vr[s], accv);
        }
        g_attn[(size_t)n * DIM + i] = accv / l;
    }
}

// ---------------------------------------------------------------------------
// Launch
// ---------------------------------------------------------------------------
extern "C" void kernel_launch(void* const* d_in, const int* in_sizes, int n_in,
                              void* d_out, int out_size)
{
    const float* x          = (const float*)d_in[0];
    const float* pos        = (const float*)d_in[1];
    const int*   attn_index = (const int*)  d_in[2];
    const int*   mask       = (const int*)  d_in[3];
    const float* Wqkv       = (const float*)d_in[4];
    const float* bqkv       = (const float*)d_in[5];
    const float* Wp1        = (const float*)d_in[6];
    const float* bp1        = (const float*)d_in[7];
    const float* Wp2        = (const float*)d_in[8];
    const float* bp2        = (const float*)d_in[9];
    const float* Wo         = (const float*)d_in[10];
    const float* bo         = (const float*)d_in[11];
    float*       out        = (float*)d_out;

    float* qkv_ptr  = nullptr;
    float* attn_ptr = nullptr;
    cudaGetSymbolAddress((void**)&qkv_ptr,  g_qkv);
    cudaGetSymbolAddress((void**)&attn_ptr, g_attn);

    // 1. pos-MLP piecewise-linear precompute
    breakpoints_kernel<<<1, PH>>>(Wp1, bp1);
    pos_coeff_kernel<<<MAXIV, DIM>>>(Wp1, bp1, Wp2);

    // 2. QKV projection: [32768,256] x [768,256]^T -> [32768,768]
    {
        dim3 grid(QKVD / BN, NPTS / BM);
        sgemm_bias_db<<<grid, 256>>>(x, Wqkv, bqkv, qkv_ptr, DIM, QKVD);
    }

    // 3. Fused gather + pos bias + per-channel softmax + value reduce
    attn_kernel<<<NPTS, DIM>>>(pos, attn_index, mask, bp2);

    // 4. Output projection: [32768,256] x [256,256]^T -> [32768,256]
    {
        dim3 grid(DIM / BN, NPTS / BM);
        sgemm_bias_db<<<grid, 256>>>(attn_ptr, Wo, bo, out, DIM, DIM);
    }
}